// round 9
// baseline (speedup 1.0000x reference)
#include <cuda_runtime.h>
#include <cuda_bf16.h>
#include <cuda_fp8.h>
#include <cstdint>

// ============================================================================
// VQ-VAE vector quantizer — sm_100 (compute_100 PTX; NO tcgen05).
// FP8 e4m3 HMMA GEMM (mma.sync.m16n8k32) for d_out + top-2/16-col candidates;
// margin-filtered exact fp32 rescore that SIMULATES the reference fp32 grid:
//     d = fl( fl(zn + en) - 2*S ), zn/en sequential ascending fp32 sums,
// argmin strict-< (lower index wins ties) over rounded values.
//
// embedding pre-scaled x1024 (exact pow2) into fp8; S descaled by 2^-9.
// MARGIN 1.5e-2 = ~13 sigma of fp8 pair-difference error.
// Single gemm launch (R7/R8's split-launch profiling trick correlated with
// container-killing ncu replay wedge; reverted).
//
// Outputs (flattened f32 tuple):
//   [0, 8388608)      z_q_out  (NCHW)
//   [8388608]         loss
//   [8388609,8421377) min_idx as float
//   [8421377,...)     d_out [N,1024]
// ============================================================================

#define N_TOK   32768
#define C_DIM   256
#define N_E     1024
#define T_TILES 256
#define C8_T    8
#define KQ_N    4
#define TILE_A8 8192          // bytes: 128 rows x 64 ch fp8, fragment order
#define TILE_B8 8192          // bytes: 128 codes x 64 ch fp8, fragment order
#define FINF    3.402823466e+38f
#define MARGIN2 1.5e-2f

#define OUT_ZQ   0ull
#define OUT_LOSS 8388608ull
#define OUT_IDX  8388609ull
#define OUT_D    8421377ull

#define GEMM_SMEM 69632       // 4 chunks x 16KB stages; epilogue overlays (67.6KB)

// ---------------- device scratch --------------------------------------------
__device__ uint4  g_A8[T_TILES * KQ_N * (TILE_A8 / 16)];   // 8 MB fp8 z fragments
__device__ uint4  g_B8[C8_T * KQ_N * (TILE_B8 / 16)];      // 256 KB fp8 e fragments
__device__ float  g_znp[T_TILES * KQ_N * 128];             // z-norm partials
__device__ float  g_enp[C8_T * KQ_N * 128];                // e-norm partials
__device__ float  g_enq[N_E];                              // e-norm, exact sequential
__device__ float2 g_cand[(size_t)N_TOK * 128];             // top2 x 16-col groups
__device__ double g_lossp[1024];

// ---------------- helpers ----------------------------------------------------
static __device__ __forceinline__ uint32_t smem_u32(const void* p) {
    uint32_t a;
    asm("{ .reg .u64 t; cvta.to.shared.u64 t, %1; cvt.u32.u64 %0, t; }"
        : "=r"(a) : "l"(p));
    return a;
}
#define MBAR_INIT(m, cnt) \
    asm volatile("mbarrier.init.shared.b64 [%0], %1;" :: "r"(m), "r"((uint32_t)(cnt)) : "memory")
#define MBAR_EXPECT_TX(m, bytes) \
    asm volatile("mbarrier.arrive.expect_tx.shared.b64 _, [%0], %1;" :: "r"(m), "r"((uint32_t)(bytes)) : "memory")
static __device__ __forceinline__ void mbar_wait(uint32_t mbar, uint32_t parity) {
    asm volatile(
        "{\n\t.reg .pred P;\n\t"
        "WL_%=:\n\t"
        "mbarrier.try_wait.parity.acquire.cta.shared::cta.b64 P, [%0], %1, 0x989680;\n\t"
        "@P bra.uni WD_%=;\n\t"
        "bra.uni WL_%=;\n\t"
        "WD_%=:\n\t}"
        :: "r"(mbar), "r"(parity) : "memory");
}
static __device__ __forceinline__ void bulk_g2s(uint32_t dst, const void* src,
                                                uint32_t bytes, uint32_t mbar) {
    asm volatile(
        "cp.async.bulk.shared::cluster.global.mbarrier::complete_tx::bytes [%0], [%1], %2, [%3];"
        :: "r"(dst), "l"(src), "r"(bytes), "r"(mbar) : "memory");
}
#define MMA_FP8(c, a, b0, b1) \
    asm volatile("mma.sync.aligned.m16n8k32.row.col.f32.e4m3.e4m3.f32 " \
                 "{%0,%1,%2,%3}, {%4,%5,%6,%7}, {%8,%9}, {%0,%1,%2,%3};" \
                 : "+f"((c)[0]), "+f"((c)[1]), "+f"((c)[2]), "+f"((c)[3]) \
                 : "r"((a)[0]), "r"((a)[1]), "r"((a)[2]), "r"((a)[3]), "r"(b0), "r"(b1))

static __device__ __forceinline__ uint8_t to_e4m3(float v) {
    return (uint8_t)__nv_cvt_float_to_fp8(v, __NV_SATFINITE, __NV_E4M3);
}
static __device__ __forceinline__ void top2_ins(float v, int i,
                                                float& v1, int& i1,
                                                float& v2, int& i2) {
    bool lt1 = (v < v1) || (v == v1 && i < i1);
    if (lt1) { v2 = v1; i2 = i1; v1 = v; i1 = i; }
    else {
        bool lt2 = (v < v2) || (v == v2 && i < i2);
        if (lt2) { v2 = v; i2 = i; }
    }
}

// ============================================================================
// prep_a: z (NCHW f32) -> fp8 fragment-ordered tiles + per-token norm partials.
// ============================================================================
__global__ void prep_a_kernel(const float* __restrict__ z) {
    int kq = blockIdx.x, t = blockIdx.y;
    int n0 = t * 128, b = n0 >> 10, s0 = n0 & 1023;
    __shared__ float s_f[64 * 132];      // [cc][token], stride 132
    __shared__ float s_part[128];
    int tid = threadIdx.x;
    int j = tid & 127;
    float acc = 0.0f;
    for (int i = tid; i < 8192; i += 256) {
        int cc = i >> 7;
        float v = z[(((size_t)(b * C_DIM + kq * 64 + cc)) << 10) + s0 + j];
        acc += v * v;
        s_f[cc * 132 + j] = v;
    }
    if (tid < 128) s_part[j] = acc;
    __syncthreads();
    if (tid >= 128) s_part[j] += acc;    // fixed order: deterministic
    __syncthreads();
    if (tid < 128) g_znp[(t * 4 + kq) * 128 + j] = s_part[j];

    uint4* dst = g_A8 + (size_t)(t * 4 + kq) * (TILE_A8 / 16);
    #pragma unroll
    for (int rep = 0; rep < 2; rep++) {
        int slot = tid + rep * 256;      // 512 slots
        int mblk = slot >> 6, ks = (slot >> 5) & 1, ln = slot & 31;
        int g = ln >> 2, tig = ln & 3;
        int r0 = mblk * 16 + g, r1 = r0 + 8;
        int cb = ks * 32 + tig * 4;
        uint8_t by[16];
        #pragma unroll
        for (int q = 0; q < 4; q++) {
            by[q]      = to_e4m3(s_f[(cb + q) * 132 + r0]);
            by[4 + q]  = to_e4m3(s_f[(cb + q) * 132 + r1]);
            by[8 + q]  = to_e4m3(s_f[(cb + 16 + q) * 132 + r0]);
            by[12 + q] = to_e4m3(s_f[(cb + 16 + q) * 132 + r1]);
        }
        dst[slot] = *(const uint4*)by;
    }
}

// ============================================================================
// prep_b: embedding -> fp8 (x1024) fragment tiles + norm partials + exact enq.
// ============================================================================
__global__ void prep_b_kernel(const float* __restrict__ e) {
    int kq = blockIdx.x, c8 = blockIdx.y;
    int tid = threadIdx.x;               // 128
    {
        int k = c8 * 128 + tid;
        float acc = 0.0f;
        for (int cc = 0; cc < 64; cc++) {
            float v = e[(size_t)k * C_DIM + kq * 64 + cc];
            acc += v * v;
        }
        g_enp[(c8 * 4 + kq) * 128 + tid] = acc;
        if (kq == 0) {
            float a = 0.0f;
            for (int c = 0; c < C_DIM; c++) {
                float v = e[(size_t)k * C_DIM + c];
                a = __fadd_rn(a, __fmul_rn(v, v));
            }
            g_enq[k] = a;
        }
    }
    uint64_t* dst = (uint64_t*)(g_B8 + (size_t)(c8 * 4 + kq) * (TILE_B8 / 16));
    #pragma unroll
    for (int rep = 0; rep < 8; rep++) {
        int slot = tid + rep * 128;      // 1024 slots of 8B
        int nblk = slot >> 6, ks = (slot >> 5) & 1, ln = slot & 31;
        int n = c8 * 128 + nblk * 8 + (ln >> 2);
        int cb = kq * 64 + ks * 32 + (ln & 3) * 4;
        const float* er = e + (size_t)n * C_DIM;
        uint8_t by[8];
        #pragma unroll
        for (int q = 0; q < 4; q++) {
            by[q]     = to_e4m3(er[cb + q]      * 1024.0f);
            by[4 + q] = to_e4m3(er[cb + 16 + q] * 1024.0f);
        }
        dst[slot] = *(const uint64_t*)by;
    }
}

// ============================================================================
// gemm: 128x128 tile, K=256 = 4 chunks all resident in smem (no mid syncs).
// 8 warps (2M x 4N), warp 64x32, mma m16n8k32 e4m3. Single launch, 2048 blocks.
// ============================================================================
extern __shared__ char dynsmem[];

__global__ void __launch_bounds__(256) gemm_kernel(float* __restrict__ out) {
    __shared__ float s_zn[128];
    __shared__ float s_en[128];
    __shared__ __align__(8) unsigned long long s_mbar[4];

    int bx = blockIdx.x;
    int tId = bx >> 3, c8 = bx & 7;
    int tid = threadIdx.x, lane = tid & 31, wid = tid >> 5;
    int wm = wid >> 2, wn = wid & 3;

    uint32_t sbase = (smem_u32(dynsmem) + 1023u) & ~1023u;
    uint32_t mb[4];
    #pragma unroll
    for (int k = 0; k < 4; k++) mb[k] = smem_u32(&s_mbar[k]);
    if (tid == 0) {
        #pragma unroll
        for (int k = 0; k < 4; k++) MBAR_INIT(mb[k], 1);
    }
    if (tid < 128) {
        float a = 0.0f;
        #pragma unroll
        for (int kq = 0; kq < 4; kq++) a += g_znp[(tId * 4 + kq) * 128 + tid];
        s_zn[tid] = a;
    } else {
        int c = tid - 128;
        float a = 0.0f;
        #pragma unroll
        for (int kq = 0; kq < 4; kq++) a += g_enp[(c8 * 4 + kq) * 128 + c];
        s_en[c] = a;
    }
    __syncthreads();   // mbar init + norms visible

    if (tid == 0) {
        const char* gA = (const char*)(g_A8 + (size_t)tId * 4 * (TILE_A8 / 16));
        const char* gB = (const char*)(g_B8 + (size_t)c8 * 4 * (TILE_B8 / 16));
        #pragma unroll
        for (int kq = 0; kq < 4; kq++) {
            MBAR_EXPECT_TX(mb[kq], TILE_A8 + TILE_B8);
            bulk_g2s(sbase + kq * 16384,        gA + (size_t)kq * TILE_A8, TILE_A8, mb[kq]);
            bulk_g2s(sbase + kq * 16384 + 8192, gB + (size_t)kq * TILE_B8, TILE_B8, mb[kq]);
        }
    }

    float c_[4][4][4];
    #pragma unroll
    for (int i = 0; i < 4; i++)
        #pragma unroll
        for (int j = 0; j < 4; j++)
            #pragma unroll
            for (int k = 0; k < 4; k++) c_[i][j][k] = 0.0f;

    #pragma unroll
    for (int kq = 0; kq < 4; kq++) {
        mbar_wait(mb[kq], 0u);
        uint32_t sA = sbase + kq * 16384;
        uint32_t sB = sA + 8192;
        #pragma unroll
        for (int ks = 0; ks < 2; ks++) {
            uint32_t a[4][4];
            uint32_t bb[4][2];
            #pragma unroll
            for (int i = 0; i < 4; i++) {
                uint32_t ad = sA + (uint32_t)(((wm * 4 + i) * 2 + ks) * 512 + lane * 16);
                asm volatile("ld.shared.v4.b32 {%0,%1,%2,%3}, [%4];"
                             : "=r"(a[i][0]), "=r"(a[i][1]), "=r"(a[i][2]), "=r"(a[i][3])
                             : "r"(ad));
            }
            #pragma unroll
            for (int j = 0; j < 4; j++) {
                uint32_t bd = sB + (uint32_t)(((wn * 4 + j) * 2 + ks) * 256 + lane * 8);
                asm volatile("ld.shared.v2.b32 {%0,%1}, [%2];"
                             : "=r"(bb[j][0]), "=r"(bb[j][1]) : "r"(bd));
            }
            #pragma unroll
            for (int i = 0; i < 4; i++)
                #pragma unroll
                for (int j = 0; j < 4; j++)
                    MMA_FP8(c_[i][j], a[i], bb[j][0], bb[j][1]);
        }
    }
    __syncthreads();   // stages dead; epilogue overlays smem

    // ---- epilogue: d -> smem stage (stride 132) + top-2 per 16-col group ----
    float* sd = (float*)dynsmem;         // 128 x 132 floats = 67584 B
    int g = lane >> 2, q = lane & 3;
    #pragma unroll
    for (int i = 0; i < 4; i++) {
        #pragma unroll
        for (int h = 0; h < 2; h++) {
            int rl = wm * 64 + i * 16 + h * 8 + g;
            int row_g = tId * 128 + rl;
            float zn = s_zn[rl];
            float v1 = FINF, v2 = FINF;
            int i1 = 0x7fffffff, i2 = 0x7fffffff;
            #pragma unroll
            for (int j = 0; j < 4; j++) {
                int cl = wn * 32 + j * 8 + q * 2;
                // d = zn + en - 2*S/1024  (S accumulated with e*1024)
                float d0 = fmaf(-0.001953125f, c_[i][j][h * 2 + 0], zn + s_en[cl]);
                float d1 = fmaf(-0.001953125f, c_[i][j][h * 2 + 1], zn + s_en[cl + 1]);
                *(float2*)&sd[rl * 132 + cl] = make_float2(d0, d1);
                top2_ins(d0, cl,     v1, i1, v2, i2);
                top2_ins(d1, cl + 1, v1, i1, v2, i2);
            }
            {   // merge lane pairs (q0+q1, q2+q3): 16-col groups
                float ov1 = __shfl_xor_sync(0xffffffffu, v1, 1);
                int   oi1 = __shfl_xor_sync(0xffffffffu, i1, 1);
                float ov2 = __shfl_xor_sync(0xffffffffu, v2, 1);
                int   oi2 = __shfl_xor_sync(0xffffffffu, i2, 1);
                top2_ins(ov1, oi1, v1, i1, v2, i2);
                top2_ins(ov2, oi2, v1, i1, v2, i2);
            }
            if ((q & 1) == 0) {
                size_t cb = (size_t)row_g * 128 + (size_t)(c8 * 16 + wn * 4 + (q >> 1) * 2);
                g_cand[cb]     = make_float2(v1, (float)(c8 * 128 + i1));
                g_cand[cb + 1] = make_float2(v2, (float)(c8 * 128 + i2));
            }
        }
    }
    __syncthreads();

    // coalesced d_out store: warp per row, 4 chunks of 32 cols
    float* dbase = out + OUT_D + (size_t)(tId * 128) * 1024 + (size_t)(c8 * 128);
    #pragma unroll
    for (int it = 0; it < 16; it++) {
        int r = wid + it * 8;
        const float* sr = sd + r * 132;
        float* dp = dbase + (size_t)r * 1024;
        #pragma unroll
        for (int cchunk = 0; cchunk < 4; cchunk++)
            dp[cchunk * 32 + lane] = sr[cchunk * 32 + lane];
    }
}

// ============================================================================
// rescore: margin-filtered exact rescore (reference-grid simulation) + gather.
// ============================================================================
__global__ void __launch_bounds__(256) rescore_kernel(const float* __restrict__ z,
                                                      const float* __restrict__ e,
                                                      float* __restrict__ out) {
    int gblk = blockIdx.x;
    int base = gblk * 32, b = base >> 10, s0 = base & 1023;
    __shared__ float s_z[C_DIM * 33];
    __shared__ float s_zn[32];
    __shared__ int   s_win[32];
    __shared__ float s_red[8];
    int tid = threadIdx.x, lane = tid & 31, w = tid >> 5;

    for (int c = w; c < C_DIM; c += 8)
        s_z[c * 33 + lane] = z[(((size_t)(b * C_DIM + c)) << 10) + s0 + lane];
    __syncthreads();

    if (w == 0) {   // exact sequential zn (reference reduction order)
        float a = 0.0f;
        for (int c = 0; c < C_DIM; c++) {
            float v = s_z[c * 33 + lane];
            a = __fadd_rn(a, __fmul_rn(v, v));
        }
        s_zn[lane] = a;
    }
    __syncthreads();

    #pragma unroll
    for (int u = 0; u < 4; u++) {
        int tt = w * 4 + u;
        int token = base + tt;
        float2 cd[4];
        unsigned long long kb = ~0ull;
        #pragma unroll
        for (int s = 0; s < 4; s++) {
            cd[s] = g_cand[(size_t)token * 128 + s * 32 + lane];
            unsigned long long kk =
                ((unsigned long long)__float_as_uint(cd[s].x) << 32) | (unsigned)(int)cd[s].y;
            if (kk < kb) kb = kk;
        }
        #pragma unroll
        for (int off = 16; off > 0; off >>= 1) {
            unsigned long long ok = __shfl_xor_sync(0xffffffffu, kb, off);
            if (ok < kb) kb = ok;
        }
        float thr = __uint_as_float((unsigned)(kb >> 32)) + MARGIN2;
        unsigned m[4];
        int tot = 0;
        #pragma unroll
        for (int s = 0; s < 4; s++) {
            m[s] = __ballot_sync(0xffffffffu, cd[s].x <= thr);
            tot += __popc(m[s]);
        }
        int winner;
        if (tot == 1) {
            winner = (int)(unsigned)(kb & 0xffffffffu);
        } else {
            float zn = s_zn[tt];
            float best = FINF;
            int bi = 0x7fffffff;
            #pragma unroll
            for (int s = 0; s < 4; s++) {
                unsigned mm = m[s];
                while (mm) {
                    int src = __ffs(mm) - 1;
                    mm &= mm - 1;
                    float fy = __shfl_sync(0xffffffffu, cd[s].y, src);
                    int ci = (int)fy;
                    const float* er = e + (size_t)ci * C_DIM;
                    float p = 0.0f;
                    #pragma unroll
                    for (int k = 0; k < 8; k++)
                        p = fmaf(er[lane + 32 * k], s_z[(lane + 32 * k) * 33 + tt], p);
                    #pragma unroll
                    for (int off = 16; off > 0; off >>= 1)
                        p += __shfl_xor_sync(0xffffffffu, p, off);
                    float t1 = __fadd_rn(zn, g_enq[ci]);
                    float d  = __fsub_rn(t1, __fmul_rn(2.0f, p));
                    if (d < best || (d == best && ci < bi)) { best = d; bi = ci; }
                }
            }
            winner = bi;
        }
        if (lane == 0) {
            s_win[tt] = winner;
            out[OUT_IDX + token] = (float)winner;
        }
    }
    __syncthreads();

    float acc = 0.0f;
    #pragma unroll
    for (int rep = 0; rep < 4; rep++) {
        int tt = w + rep * 8;
        int chosen = s_win[tt];
        #pragma unroll
        for (int k = 0; k < 8; k++) {
            int c = lane + 32 * k;
            float ev = e[(size_t)chosen * C_DIM + c];
            float zv = s_z[c * 33 + tt];
            float diff = ev - zv;
            s_z[c * 33 + tt] = zv + diff;
            acc += diff * diff;
        }
    }
    #pragma unroll
    for (int off = 16; off > 0; off >>= 1)
        acc += __shfl_xor_sync(0xffffffffu, acc, off);
    if (lane == 0) s_red[w] = acc;
    __syncthreads();
    if (tid == 0) {
        double t = 0.0;
        #pragma unroll
        for (int k = 0; k < 8; k++) t += (double)s_red[k];
        g_lossp[gblk] = t;
    }
    __syncthreads();
    for (int c = w; c < C_DIM; c += 8)
        out[OUT_ZQ + (((size_t)(b * C_DIM + c)) << 10) + s0 + lane] = s_z[c * 33 + lane];
}

// ============================================================================
__global__ void finalize_kernel(float* __restrict__ out) {
    __shared__ double sr[256];
    int tid = threadIdx.x;
    double a = 0.0;
    #pragma unroll
    for (int k = 0; k < 4; k++) a += g_lossp[tid * 4 + k];
    sr[tid] = a;
    __syncthreads();
    for (int st = 128; st > 0; st >>= 1) {
        if (tid < st) sr[tid] += sr[tid + st];
        __syncthreads();
    }
    if (tid == 0) out[OUT_LOSS] = (float)(1.25 * sr[0] / 8388608.0);
}

// ============================================================================
extern "C" void kernel_launch(void* const* d_in, const int* in_sizes, int n_in,
                              void* d_out, int out_size) {
    const float* z   = (const float*)d_in[0];
    const float* emb = (const float*)d_in[1];
    if (n_in >= 2 && in_sizes[0] == N_E * C_DIM) {
        emb = (const float*)d_in[0];
        z   = (const float*)d_in[1];
    }
    float* out = (float*)d_out;

    cudaFuncSetAttribute(gemm_kernel,
                         cudaFuncAttributeMaxDynamicSharedMemorySize, GEMM_SMEM);

    prep_a_kernel<<<dim3(KQ_N, T_TILES), 256>>>(z);
    prep_b_kernel<<<dim3(KQ_N, C8_T), 128>>>(emb);
    gemm_kernel<<<T_TILES * C8_T, 256, GEMM_SMEM>>>(out);
    rescore_kernel<<<N_TOK / 32, 256>>>(z, emb, out);
    finalize_kernel<<<1, 256>>>(out);
}